// round 6
// baseline (speedup 1.0000x reference)
#include <cuda_runtime.h>
#include <cuda_fp16.h>

#define B 512
#define D 128
#define JT 64            // j per block
#define IB 2             // i per block

// ---------------- device scratch (no allocation allowed) ----------------
__device__ float  g_e1n[3][B][D];     // normalized emb1, row-major [l][i][d]
__device__ __half g_e2nTh[3][D][B];   // normalized emb2, fp16, transposed [l][d][j]
__device__ float  g_c1p[2][B][D];     // cert1_{1,2} * 0.5*alpha_{1,2}
__device__ __half g_c2Th[2][D][B];    // cert2_{1,2}, fp16, transposed [l][d][j]
__device__ float  g_bp[2][D];         // 0.5*beta_{1,2}
__device__ uint4  g_wH[2][D];         // .x/.y/.z = broadcast half2 of w0..w2, .w = packed idx

__device__ __forceinline__ float tanh_approx(float x) {
    float y;
    asm("tanh.approx.f32 %0, %1;" : "=f"(y) : "f"(x));
    return y;
}
__device__ __forceinline__ __half2 u2h(unsigned x) {
    __half2 h; *(unsigned*)&h = x; return h;
}
__device__ __forceinline__ unsigned pack2(float a, float b) {
    __half2 h = __floats2half2_rn(a, b); return *(unsigned*)&h;
}
__device__ __forceinline__ float blend(float a, float e2, float cp, float c2,
                                       float bp, float s) {
    float v = a - e2, n = v * v;
    float P = fmaf(0.5f, tanh_approx(fmaf(cp, c2, bp)), 0.5f);
    return fmaf(P, n - s, s);
}

// ---------------- prep: normalize / transpose / scale / topk ----------------
__global__ void prep_kernel(
    const float* __restrict__ e1_0, const float* __restrict__ e1_1, const float* __restrict__ e1_2,
    const float* __restrict__ e2_0, const float* __restrict__ e2_1, const float* __restrict__ e2_2,
    const float* __restrict__ c1_1, const float* __restrict__ c1_2,
    const float* __restrict__ c2_1, const float* __restrict__ c2_2,
    const float* __restrict__ a_1,  const float* __restrict__ a_2,
    const float* __restrict__ b_1,  const float* __restrict__ b_2,
    const float* __restrict__ link0, const float* __restrict__ link1)
{
    __shared__ float sp[4];
    int bid = blockIdx.x;
    int d = threadIdx.x;   // 0..127

    if (bid < 3072) {
        // L2-normalize one embedding row
        int which = bid / 1536;            // 0 = emb1, 1 = emb2
        int t = bid % 1536;
        int l = t / B, r = t % B;
        const float* src = (which == 0)
            ? (l == 0 ? e1_0 : (l == 1 ? e1_1 : e1_2))
            : (l == 0 ? e2_0 : (l == 1 ? e2_1 : e2_2));
        float x = src[r * D + d];
        float ss = x * x;
        #pragma unroll
        for (int o = 16; o; o >>= 1) ss += __shfl_xor_sync(0xffffffffu, ss, o);
        if ((d & 31) == 0) sp[d >> 5] = ss;
        __syncthreads();
        float tot = sp[0] + sp[1] + sp[2] + sp[3];
        float inv = 1.0f / fmaxf(sqrtf(tot), 1e-12f);
        float v = x * inv;
        if (which == 0) g_e1n[l][r][d]   = v;
        else            g_e2nTh[l][d][r] = __float2half_rn(v);
    } else if (bid < 4096) {
        // c1p = cert1 * 0.5*alpha
        int t = bid - 3072;
        int l = t / B, r = t % B;
        const float* c = (l == 0) ? c1_1 : c1_2;
        const float* a = (l == 0) ? a_1  : a_2;
        g_c1p[l][r][d] = c[r * D + d] * (0.5f * a[d]);
    } else if (bid < 5120) {
        // cert2 transpose + fp16
        int t = bid - 4096;
        int l = t / B, r = t % B;
        const float* c = (l == 0) ? c2_1 : c2_2;
        g_c2Th[l][d][r] = __float2half_rn(c[r * D + d]);
    } else if (bid == 5120) {
        g_bp[0][d] = 0.5f * b_1[d];
        g_bp[1][d] = 0.5f * b_2[d];
    } else {
        // top-3 per column + column normalization; bid 5121 -> link0, 5122 -> link1
        int m = bid - 5121;
        int e = d;
        const float* L = m ? link1 : link0;
        float v0 = -1e30f, v1 = -1e30f, v2 = -1e30f;
        int   i0 = 0, i1 = 0, i2 = 0;
        for (int r = 0; r < D; ++r) {
            float w = L[r * D + e];     // column e, row r
            if (w > v0)      { v2 = v1; i2 = i1; v1 = v0; i1 = i0; v0 = w; i0 = r; }
            else if (w > v1) { v2 = v1; i2 = i1; v1 = w;  i1 = r; }
            else if (w > v2) { v2 = w;  i2 = r; }
        }
        float inv = 1.0f / (v0 + v1 + v2 + 1e-8f);
        unsigned h0 = (unsigned)__half_as_ushort(__float2half_rn(v0 * inv));
        unsigned h1 = (unsigned)__half_as_ushort(__float2half_rn(v1 * inv));
        unsigned h2 = (unsigned)__half_as_ushort(__float2half_rn(v2 * inv));
        g_wH[m][e] = make_uint4(h0 * 0x10001u, h1 * 0x10001u, h2 * 0x10001u,
                                (unsigned)i0 | ((unsigned)i1 << 8) | ((unsigned)i2 << 16));
    }
}

// ---------------- fused similarity kernel ----------------
// block = (16 j-quads, 64 channel-pairs) = 1024 threads; each thread:
// 2 channels x 2 i x 4 j. nh tile stored fp16 with 128B rows -> every shared
// gather/store is exactly 2 full-row wavefronts (zero conflicts). j-side
// tensors fp16 -> all LDG are 8B coalesced. All math affecting accuracy in fp32
// (einsum convex combination in HFMA2, error ~5e-4 per element, ~1e-4 after sum).
__global__ __launch_bounds__(1024, 1) void avsl_main_kernel(float* __restrict__ out)
{
    __shared__ union {
        __half nh[IB][D][JT];    // 32 KB, dead after layer-2 gathers
        float4 sRed[32][16];     // 8 KB, aliased for the final reduction
    } u;
    __shared__ uint4 sW[2][D];       // 4 KB
    __shared__ float sE0[IB][D];     // 1 KB
    __shared__ float sE1[2][IB][D];  // 2 KB
    __shared__ float sC1[2][IB][D];  // 2 KB
    __shared__ float sBP[2][D];      // 1 KB   (total static ~43 KB)

    const int q   = threadIdx.x;     // 0..15 (j-quad)
    const int g   = threadIdx.y;     // 0..63 (channel pair)
    const int tid = g * 16 + q;
    const int jj  = blockIdx.x * JT + q * 4;
    const int i_base = blockIdx.y * IB;

    // stage W + bp (one writer per word)
    if (tid < 2 * D) {
        ((uint4*)sW)[tid]  = ((const uint4*)g_wH)[tid];
        ((float*)sBP)[tid] = ((const float*)g_bp)[tid];
    }
    // stage i-side data: 5 segments x IB x D = 1280 floats
    for (int t = tid; t < 5 * IB * D; t += 1024) {
        int seg = t / (IB * D);
        int rem = t - seg * (IB * D);
        int ii = rem >> 7, d = rem & 127;
        int i = i_base + ii;
        if (seg == 0)      sE0[ii][d]          = g_e1n[0][i][d];
        else if (seg < 3)  sE1[seg - 1][ii][d] = g_e1n[seg][i][d];
        else               sC1[seg - 3][ii][d] = g_c1p[seg - 3][i][d];
    }
    __syncthreads();

    // ---- layer 0: nodes -> nh (fp16) ----
    #pragma unroll
    for (int k = 0; k < 2; ++k) {
        int e = g * 2 + k;
        uint2 e2u = *(const uint2*)&g_e2nTh[0][e][jj];
        float2 ea = __half22float2(u2h(e2u.x));
        float2 eb = __half22float2(u2h(e2u.y));
        #pragma unroll
        for (int ii = 0; ii < IB; ++ii) {
            float a = sE0[ii][e];
            float dx = a - ea.x, dy = a - ea.y, dz = a - eb.x, dw = a - eb.y;
            *(uint2*)&u.nh[ii][e][q * 4] =
                make_uint2(pack2(dx * dx, dy * dy), pack2(dz * dz, dw * dw));
        }
    }
    __syncthreads();

    // ---- layer 1 ----
    uint2 tnh[2][IB];
    #pragma unroll
    for (int k = 0; k < 2; ++k) {
        const int e = g * 2 + k;
        const uint4 W = sW[0][e];
        const __half2 w0 = u2h(W.x), w1 = u2h(W.y), w2 = u2h(W.z);
        const int o0 = (int)(W.w & 255u) * 16;
        const int o1 = (int)((W.w >> 8) & 255u) * 16;
        const int o2 = (int)((W.w >> 16) & 255u) * 16;
        uint2 e2u = *(const uint2*)&g_e2nTh[1][e][jj];
        uint2 c2u = *(const uint2*)&g_c2Th[0][e][jj];
        float2 e2a = __half22float2(u2h(e2u.x)), e2b = __half22float2(u2h(e2u.y));
        float2 c2a = __half22float2(u2h(c2u.x)), c2b = __half22float2(u2h(c2u.y));
        const float bp = sBP[0][e];
        #pragma unroll
        for (int ii = 0; ii < IB; ++ii) {
            const uint2* nb = (const uint2*)&u.nh[ii][0][0];
            uint2 r0 = nb[o0 + q], r1 = nb[o1 + q], r2 = nb[o2 + q];
            __half2 sA = __hfma2(w2, u2h(r2.x), __hfma2(w1, u2h(r1.x), __hmul2(w0, u2h(r0.x))));
            __half2 sB = __hfma2(w2, u2h(r2.y), __hfma2(w1, u2h(r1.y), __hmul2(w0, u2h(r0.y))));
            float2 s0 = __half22float2(sA), s1 = __half22float2(sB);
            const float a = sE1[0][ii][e], cp = sC1[0][ii][e];
            float rx = blend(a, e2a.x, cp, c2a.x, bp, s0.x);
            float ry = blend(a, e2a.y, cp, c2a.y, bp, s0.y);
            float rz = blend(a, e2b.x, cp, c2b.x, bp, s1.x);
            float rw = blend(a, e2b.y, cp, c2b.y, bp, s1.y);
            tnh[k][ii] = make_uint2(pack2(rx, ry), pack2(rz, rw));
        }
    }
    __syncthreads();   // all layer-1 gathers done before overwrite
    #pragma unroll
    for (int k = 0; k < 2; ++k)
        #pragma unroll
        for (int ii = 0; ii < IB; ++ii)
            *(uint2*)&u.nh[ii][g * 2 + k][q * 4] = tnh[k][ii];
    __syncthreads();

    // ---- layer 2 + channel accumulation (fp32) ----
    float4 acc[IB];
    #pragma unroll
    for (int ii = 0; ii < IB; ++ii) acc[ii] = make_float4(0.f, 0.f, 0.f, 0.f);
    #pragma unroll
    for (int k = 0; k < 2; ++k) {
        const int e = g * 2 + k;
        const uint4 W = sW[1][e];
        const __half2 w0 = u2h(W.x), w1 = u2h(W.y), w2 = u2h(W.z);
        const int o0 = (int)(W.w & 255u) * 16;
        const int o1 = (int)((W.w >> 8) & 255u) * 16;
        const int o2 = (int)((W.w >> 16) & 255u) * 16;
        uint2 e2u = *(const uint2*)&g_e2nTh[2][e][jj];
        uint2 c2u = *(const uint2*)&g_c2Th[1][e][jj];
        float2 e2a = __half22float2(u2h(e2u.x)), e2b = __half22float2(u2h(e2u.y));
        float2 c2a = __half22float2(u2h(c2u.x)), c2b = __half22float2(u2h(c2u.y));
        const float bp = sBP[1][e];
        #pragma unroll
        for (int ii = 0; ii < IB; ++ii) {
            const uint2* nb = (const uint2*)&u.nh[ii][0][0];
            uint2 r0 = nb[o0 + q], r1 = nb[o1 + q], r2 = nb[o2 + q];
            __half2 sA = __hfma2(w2, u2h(r2.x), __hfma2(w1, u2h(r1.x), __hmul2(w0, u2h(r0.x))));
            __half2 sB = __hfma2(w2, u2h(r2.y), __hfma2(w1, u2h(r1.y), __hmul2(w0, u2h(r0.y))));
            float2 s0 = __half22float2(sA), s1 = __half22float2(sB);
            const float a = sE1[1][ii][e], cp = sC1[1][ii][e];
            acc[ii].x += blend(a, e2a.x, cp, c2a.x, bp, s0.x);
            acc[ii].y += blend(a, e2a.y, cp, c2a.y, bp, s0.y);
            acc[ii].z += blend(a, e2b.x, cp, c2b.x, bp, s1.x);
            acc[ii].w += blend(a, e2b.y, cp, c2b.y, bp, s1.y);
        }
    }
    __syncthreads();   // nh dead from here: sRed alias is safe

    // fold the 2 channel-pairs sharing a warp (lane = (g&1)*16 + q)
    #pragma unroll
    for (int ii = 0; ii < IB; ++ii) {
        acc[ii].x += __shfl_down_sync(0xffffffffu, acc[ii].x, 16);
        acc[ii].y += __shfl_down_sync(0xffffffffu, acc[ii].y, 16);
        acc[ii].z += __shfl_down_sync(0xffffffffu, acc[ii].z, 16);
        acc[ii].w += __shfl_down_sync(0xffffffffu, acc[ii].w, 16);
    }
    const int w = tid >> 5, lane = tid & 31;
    #pragma unroll
    for (int ii = 0; ii < IB; ++ii) {
        if (lane < 16) u.sRed[w][lane] = acc[ii];
        __syncthreads();
        if (tid < 16) {
            float4 tot = make_float4(0.f, 0.f, 0.f, 0.f);
            #pragma unroll
            for (int ww = 0; ww < 32; ++ww) {
                float4 t = u.sRed[ww][tid];
                tot.x += t.x; tot.y += t.y; tot.z += t.z; tot.w += t.w;
            }
            *(float4*)&out[(i_base + ii) * B + blockIdx.x * JT + tid * 4] = tot;
        }
        __syncthreads();
    }
}

// ---------------- launch ----------------
extern "C" void kernel_launch(void* const* d_in, const int* in_sizes, int n_in,
                              void* d_out, int out_size)
{
    (void)n_in; (void)out_size;

    const float *e1_0, *e1_1, *e1_2, *e2_0, *e2_1, *e2_2;
    const float *c1_1, *c1_2, *c2_1, *c2_2;
    const float *a_1, *a_2, *b_1, *b_2;
    const float *link0, *link1;

    // Detect input ordering at runtime via element counts (see round-1 note).
    if (in_sizes[4] == 128) {
        // dict insertion order (interleaved per layer)
        e1_0 = (const float*)d_in[0];   e2_0 = (const float*)d_in[1];
        e1_1 = (const float*)d_in[6];   e2_1 = (const float*)d_in[7];
        e1_2 = (const float*)d_in[12];  e2_2 = (const float*)d_in[13];
        c1_1 = (const float*)d_in[8];   c2_1 = (const float*)d_in[9];
        c1_2 = (const float*)d_in[14];  c2_2 = (const float*)d_in[15];
        a_1  = (const float*)d_in[10];  b_1  = (const float*)d_in[11];
        a_2  = (const float*)d_in[16];  b_2  = (const float*)d_in[17];
        link0 = (const float*)d_in[18]; link1 = (const float*)d_in[19];
    } else {
        // function-signature order (grouped)
        e1_0 = (const float*)d_in[0];   e1_1 = (const float*)d_in[1];
        e1_2 = (const float*)d_in[2];
        e2_0 = (const float*)d_in[3];   e2_1 = (const float*)d_in[4];
        e2_2 = (const float*)d_in[5];
        c1_1 = (const float*)d_in[7];   c1_2 = (const float*)d_in[8];
        c2_1 = (const float*)d_in[10];  c2_2 = (const float*)d_in[11];
        a_1  = (const float*)d_in[13];  a_2  = (const float*)d_in[14];
        b_1  = (const float*)d_in[16];  b_2  = (const float*)d_in[17];
        link0 = (const float*)d_in[18]; link1 = (const float*)d_in[19];
    }

    prep_kernel<<<5123, 128>>>(e1_0, e1_1, e1_2, e2_0, e2_1, e2_2,
                               c1_1, c1_2, c2_1, c2_2, a_1, a_2, b_1, b_2,
                               link0, link1);

    dim3 grid(B / JT, B / IB);   // (8, 256)
    dim3 blk(16, 64);
    avsl_main_kernel<<<grid, blk>>>((float*)d_out);
}

// round 7
// speedup vs baseline: 1.2341x; 1.2341x over previous
#include <cuda_runtime.h>
#include <cuda_fp16.h>

#define B 512
#define D 128
#define JT 64            // j per block

// ---------------- device scratch (no allocation allowed) ----------------
__device__ float  g_e1n[3][B][D];     // normalized emb1, row-major [l][i][d]
__device__ __half g_e2nTh[3][D][B];   // normalized emb2, fp16, transposed [l][d][j]
__device__ float  g_c1p[2][B][D];     // cert1_{1,2} * 0.5*alpha_{1,2}
__device__ __half g_c2Th[2][D][B];    // cert2_{1,2}, fp16, transposed [l][d][j]
__device__ float  g_bp[2][D];         // 0.5*beta_{1,2}
__device__ uint4  g_wH[2][D];         // .x/.y/.z = broadcast half2 of w0..w2, .w = packed idx

__device__ __forceinline__ __half2 u2h(unsigned x) {
    __half2 h; *(unsigned*)&h = x; return h;
}
__device__ __forceinline__ unsigned h2u(__half2 h) {
    return *(unsigned*)&h;
}
__device__ __forceinline__ __half2 tanh2(__half2 x) {
    unsigned xi = h2u(x), yo;
    asm("tanh.approx.f16x2 %0, %1;" : "=r"(yo) : "r"(xi));
    return u2h(yo);
}
// r = s + P*(n-s),  n = (a-e2)^2,  P = 0.5*tanh(cp*c2+bp)+0.5   (all half2)
__device__ __forceinline__ __half2 blend2(__half2 ha, __half2 e2, __half2 cp,
                                          __half2 c2, __half2 bp, __half2 s,
                                          __half2 H05) {
    __half2 v = __hsub2(ha, e2);
    __half2 n = __hmul2(v, v);
    __half2 P = __hfma2(H05, tanh2(__hfma2(cp, c2, bp)), H05);
    return __hfma2(P, __hsub2(n, s), s);
}

// ---------------- prep: normalize / transpose / scale / topk ----------------
__global__ void prep_kernel(
    const float* __restrict__ e1_0, const float* __restrict__ e1_1, const float* __restrict__ e1_2,
    const float* __restrict__ e2_0, const float* __restrict__ e2_1, const float* __restrict__ e2_2,
    const float* __restrict__ c1_1, const float* __restrict__ c1_2,
    const float* __restrict__ c2_1, const float* __restrict__ c2_2,
    const float* __restrict__ a_1,  const float* __restrict__ a_2,
    const float* __restrict__ b_1,  const float* __restrict__ b_2,
    const float* __restrict__ link0, const float* __restrict__ link1)
{
    __shared__ float sp[4];
    int bid = blockIdx.x;
    int d = threadIdx.x;   // 0..127

    if (bid < 3072) {
        // L2-normalize one embedding row
        int which = bid / 1536;            // 0 = emb1, 1 = emb2
        int t = bid % 1536;
        int l = t / B, r = t % B;
        const float* src = (which == 0)
            ? (l == 0 ? e1_0 : (l == 1 ? e1_1 : e1_2))
            : (l == 0 ? e2_0 : (l == 1 ? e2_1 : e2_2));
        float x = src[r * D + d];
        float ss = x * x;
        #pragma unroll
        for (int o = 16; o; o >>= 1) ss += __shfl_xor_sync(0xffffffffu, ss, o);
        if ((d & 31) == 0) sp[d >> 5] = ss;
        __syncthreads();
        float tot = sp[0] + sp[1] + sp[2] + sp[3];
        float inv = 1.0f / fmaxf(sqrtf(tot), 1e-12f);
        float v = x * inv;
        if (which == 0) g_e1n[l][r][d]   = v;
        else            g_e2nTh[l][d][r] = __float2half_rn(v);
    } else if (bid < 4096) {
        // c1p = cert1 * 0.5*alpha
        int t = bid - 3072;
        int l = t / B, r = t % B;
        const float* c = (l == 0) ? c1_1 : c1_2;
        const float* a = (l == 0) ? a_1  : a_2;
        g_c1p[l][r][d] = c[r * D + d] * (0.5f * a[d]);
    } else if (bid < 5120) {
        // cert2 transpose + fp16
        int t = bid - 4096;
        int l = t / B, r = t % B;
        const float* c = (l == 0) ? c2_1 : c2_2;
        g_c2Th[l][d][r] = __float2half_rn(c[r * D + d]);
    } else if (bid == 5120) {
        g_bp[0][d] = 0.5f * b_1[d];
        g_bp[1][d] = 0.5f * b_2[d];
    } else {
        // top-3 per column + column normalization; bid 5121 -> link0, 5122 -> link1
        int m = bid - 5121;
        int e = d;
        const float* L = m ? link1 : link0;
        float v0 = -1e30f, v1 = -1e30f, v2 = -1e30f;
        int   i0 = 0, i1 = 0, i2 = 0;
        for (int r = 0; r < D; ++r) {
            float w = L[r * D + e];     // column e, row r
            if (w > v0)      { v2 = v1; i2 = i1; v1 = v0; i1 = i0; v0 = w; i0 = r; }
            else if (w > v1) { v2 = v1; i2 = i1; v1 = w;  i1 = r; }
            else if (w > v2) { v2 = w;  i2 = r; }
        }
        float inv = 1.0f / (v0 + v1 + v2 + 1e-8f);
        unsigned h0 = (unsigned)__half_as_ushort(__float2half_rn(v0 * inv));
        unsigned h1 = (unsigned)__half_as_ushort(__float2half_rn(v1 * inv));
        unsigned h2 = (unsigned)__half_as_ushort(__float2half_rn(v2 * inv));
        g_wH[m][e] = make_uint4(h0 * 0x10001u, h1 * 0x10001u, h2 * 0x10001u,
                                (unsigned)i0 | ((unsigned)i1 << 8) | ((unsigned)i2 << 16));
    }
}

// ---------------- fused similarity kernel ----------------
// block = (16 j-quads, 32 channel-quads) = 512 threads, 2 blocks/SM;
// each thread: 4 channels x 4 j, one i-row per block. Everything except the
// final channel sum runs in half2 (incl. tanh.approx.f16x2). nh rows are
// exactly 128B -> all gathers/stores conflict-free; all LDG 8B coalesced.
__global__ __launch_bounds__(512, 2) void avsl_main_kernel(float* __restrict__ out)
{
    __shared__ union {
        __half nh[D][JT];        // 16 KB, dead after layer-2 gathers
        float4 sRed[16][16];     // 4 KB, aliased for the final reduction
    } u;
    __shared__ uint4    sW[2][D];    // 4 KB
    __shared__ unsigned sIh[5][D];   // 2.5 KB: broadcast-half2 of e1n l0..2, c1p l1..2
    __shared__ unsigned sBPh[2][D];  // 1 KB:  broadcast-half2 of bp

    const int q   = threadIdx.x;     // 0..15 (j-quad)
    const int g   = threadIdx.y;     // 0..31 (channel quad)
    const int tid = g * 16 + q;
    const int jj  = blockIdx.x * JT + q * 4;
    const int i   = blockIdx.y;

    // stage W + bp (one writer per word)
    if (tid < 2 * D) {
        ((uint4*)sW)[tid] = ((const uint4*)g_wH)[tid];
        ((unsigned*)sBPh)[tid] = h2u(__float2half2_rn(((const float*)g_bp)[tid]));
    }
    // stage i-side constants as broadcast half2: 5 segments x D
    for (int t = tid; t < 5 * D; t += 512) {
        int seg = t >> 7, d = t & 127;
        float v;
        if (seg == 0)      v = g_e1n[0][i][d];
        else if (seg < 3)  v = g_e1n[seg][i][d];
        else               v = g_c1p[seg - 3][i][d];
        sIh[seg][d] = h2u(__float2half2_rn(v));
    }
    __syncthreads();

    const __half2 H05 = __float2half2_rn(0.5f);

    // ---- layer 0 ----
    #pragma unroll
    for (int k = 0; k < 4; ++k) {
        int e = g * 4 + k;
        uint2 e2u = *(const uint2*)&g_e2nTh[0][e][jj];
        __half2 ha = u2h(sIh[0][e]);
        __half2 va = __hsub2(ha, u2h(e2u.x));
        __half2 vb = __hsub2(ha, u2h(e2u.y));
        *(uint2*)&u.nh[e][q * 4] = make_uint2(h2u(__hmul2(va, va)), h2u(__hmul2(vb, vb)));
    }
    __syncthreads();

    // ---- layer 1 ----
    uint2 tnh[4];
    #pragma unroll
    for (int k = 0; k < 4; ++k) {
        const int e = g * 4 + k;
        const uint4 W = sW[0][e];
        const __half2 w0 = u2h(W.x), w1 = u2h(W.y), w2 = u2h(W.z);
        const int o0 = (int)(W.w & 255u) * 16;
        const int o1 = (int)((W.w >> 8) & 255u) * 16;
        const int o2 = (int)((W.w >> 16) & 255u) * 16;
        const uint2* nb = (const uint2*)u.nh;
        uint2 r0 = nb[o0 + q], r1 = nb[o1 + q], r2 = nb[o2 + q];
        __half2 sA = __hfma2(w2, u2h(r2.x), __hfma2(w1, u2h(r1.x), __hmul2(w0, u2h(r0.x))));
        __half2 sB = __hfma2(w2, u2h(r2.y), __hfma2(w1, u2h(r1.y), __hmul2(w0, u2h(r0.y))));
        uint2 e2u = *(const uint2*)&g_e2nTh[1][e][jj];
        uint2 c2u = *(const uint2*)&g_c2Th[0][e][jj];
        __half2 ha = u2h(sIh[1][e]);
        __half2 cp = u2h(sIh[3][e]);
        __half2 bp = u2h(sBPh[0][e]);
        __half2 rA = blend2(ha, u2h(e2u.x), cp, u2h(c2u.x), bp, sA, H05);
        __half2 rB = blend2(ha, u2h(e2u.y), cp, u2h(c2u.y), bp, sB, H05);
        tnh[k] = make_uint2(h2u(rA), h2u(rB));
    }
    __syncthreads();   // all layer-1 gathers done before overwrite
    #pragma unroll
    for (int k = 0; k < 4; ++k)
        *(uint2*)&u.nh[g * 4 + k][q * 4] = tnh[k];
    __syncthreads();

    // ---- layer 2 + channel accumulation (fp32 acc) ----
    float4 acc = make_float4(0.f, 0.f, 0.f, 0.f);
    #pragma unroll
    for (int k = 0; k < 4; ++k) {
        const int e = g * 4 + k;
        const uint4 W = sW[1][e];
        const __half2 w0 = u2h(W.x), w1 = u2h(W.y), w2 = u2h(W.z);
        const int o0 = (int)(W.w & 255u) * 16;
        const int o1 = (int)((W.w >> 8) & 255u) * 16;
        const int o2 = (int)((W.w >> 16) & 255u) * 16;
        const uint2* nb = (const uint2*)u.nh;
        uint2 r0 = nb[o0 + q], r1 = nb[o1 + q], r2 = nb[o2 + q];
        __half2 sA = __hfma2(w2, u2h(r2.x), __hfma2(w1, u2h(r1.x), __hmul2(w0, u2h(r0.x))));
        __half2 sB = __hfma2(w2, u2h(r2.y), __hfma2(w1, u2h(r1.y), __hmul2(w0, u2h(r0.y))));
        uint2 e2u = *(const uint2*)&g_e2nTh[2][e][jj];
        uint2 c2u = *(const uint2*)&g_c2Th[1][e][jj];
        __half2 ha = u2h(sIh[2][e]);
        __half2 cp = u2h(sIh[4][e]);
        __half2 bp = u2h(sBPh[1][e]);
        __half2 rA = blend2(ha, u2h(e2u.x), cp, u2h(c2u.x), bp, sA, H05);
        __half2 rB = blend2(ha, u2h(e2u.y), cp, u2h(c2u.y), bp, sB, H05);
        float2 fA = __half22float2(rA), fB = __half22float2(rB);
        acc.x += fA.x; acc.y += fA.y; acc.z += fB.x; acc.w += fB.y;
    }
    __syncthreads();   // nh dead from here: sRed alias is safe

    // fold the 2 channel-quads sharing a warp, then across warps via smem
    acc.x += __shfl_down_sync(0xffffffffu, acc.x, 16);
    acc.y += __shfl_down_sync(0xffffffffu, acc.y, 16);
    acc.z += __shfl_down_sync(0xffffffffu, acc.z, 16);
    acc.w += __shfl_down_sync(0xffffffffu, acc.w, 16);
    const int w = tid >> 5, lane = tid & 31;
    if (lane < 16) u.sRed[w][lane] = acc;
    __syncthreads();
    if (tid < 16) {
        float4 tot = make_float4(0.f, 0.f, 0.f, 0.f);
        #pragma unroll
        for (int ww = 0; ww < 16; ++ww) {
            float4 t = u.sRed[ww][tid];
            tot.x += t.x; tot.y += t.y; tot.z += t.z; tot.w += t.w;
        }
        *(float4*)&out[i * B + blockIdx.x * JT + tid * 4] = tot;
    }
}

// ---------------- launch ----------------
extern "C" void kernel_launch(void* const* d_in, const int* in_sizes, int n_in,
                              void* d_out, int out_size)
{
    (void)n_in; (void)out_size;

    const float *e1_0, *e1_1, *e1_2, *e2_0, *e2_1, *e2_2;
    const float *c1_1, *c1_2, *c2_1, *c2_2;
    const float *a_1, *a_2, *b_1, *b_2;
    const float *link0, *link1;

    // Detect input ordering at runtime via element counts (see round-1 note).
    if (in_sizes[4] == 128) {
        // dict insertion order (interleaved per layer)
        e1_0 = (const float*)d_in[0];   e2_0 = (const float*)d_in[1];
        e1_1 = (const float*)d_in[6];   e2_1 = (const float*)d_in[7];
        e1_2 = (const float*)d_in[12];  e2_2 = (const float*)d_in[13];
        c1_1 = (const float*)d_in[8];   c2_1 = (const float*)d_in[9];
        c1_2 = (const float*)d_in[14];  c2_2 = (const float*)d_in[15];
        a_1  = (const float*)d_in[10];  b_1  = (const float*)d_in[11];
        a_2  = (const float*)d_in[16];  b_2  = (const float*)d_in[17];
        link0 = (const float*)d_in[18]; link1 = (const float*)d_in[19];
    } else {
        // function-signature order (grouped)
        e1_0 = (const float*)d_in[0];   e1_1 = (const float*)d_in[1];
        e1_2 = (const float*)d_in[2];
        e2_0 = (const float*)d_in[3];   e2_1 = (const float*)d_in[4];
        e2_2 = (const float*)d_in[5];
        c1_1 = (const float*)d_in[7];   c1_2 = (const float*)d_in[8];
        c2_1 = (const float*)d_in[10];  c2_2 = (const float*)d_in[11];
        a_1  = (const float*)d_in[13];  a_2  = (const float*)d_in[14];
        b_1  = (const float*)d_in[16];  b_2  = (const float*)d_in[17];
        link0 = (const float*)d_in[18]; link1 = (const float*)d_in[19];
    }

    prep_kernel<<<5123, 128>>>(e1_0, e1_1, e1_2, e2_0, e2_1, e2_2,
                               c1_1, c1_2, c2_1, c2_2, a_1, a_2, b_1, b_2,
                               link0, link1);

    dim3 grid(B / JT, B);   // (8, 512)
    dim3 blk(16, 32);
    avsl_main_kernel<<<grid, blk>>>((float*)d_out);
}

// round 8
// speedup vs baseline: 1.2417x; 1.0061x over previous
#include <cuda_runtime.h>
#include <cuda_fp16.h>

#define B 512
#define D 128
#define JT 64            // j per block

// ---------------- device scratch (no allocation allowed) ----------------
__device__ float  g_e1n[3][B][D];     // normalized emb1, row-major [l][i][d]
__device__ __half g_e2nTh[3][D][B];   // normalized emb2, fp16, transposed [l][d][j]
__device__ float  g_c1p[2][B][D];     // cert1_{1,2} * 0.5*alpha_{1,2}
__device__ __half g_c2Th[2][D][B];    // cert2_{1,2}, fp16, transposed [l][d][j]
__device__ float  g_bp[2][D];         // 0.5*beta_{1,2}
__device__ uint4  g_wH[2][D];         // .x/.y/.z = broadcast half2 of w0..w2, .w = packed idx

__device__ __forceinline__ __half2 u2h(unsigned x) {
    __half2 h; *(unsigned*)&h = x; return h;
}
__device__ __forceinline__ unsigned h2u(__half2 h) {
    return *(unsigned*)&h;
}
__device__ __forceinline__ __half2 tanh2(__half2 x) {
    unsigned xi = h2u(x), yo;
    asm("tanh.approx.f16x2 %0, %1;" : "=r"(yo) : "r"(xi));
    return u2h(yo);
}
// r = s + P*(n-s),  n = (a-e2)^2,  P = 0.5*tanh(cp*c2+bp)+0.5   (all half2)
__device__ __forceinline__ __half2 blend2(__half2 ha, __half2 e2, __half2 cp,
                                          __half2 c2, __half2 bp, __half2 s,
                                          __half2 H05) {
    __half2 v = __hsub2(ha, e2);
    __half2 n = __hmul2(v, v);
    __half2 P = __hfma2(H05, tanh2(__hfma2(cp, c2, bp)), H05);
    return __hfma2(P, __hsub2(n, s), s);
}
// 3-term weighted sum of gathered half2s
__device__ __forceinline__ __half2 ws3(__half2 w0, __half2 w1, __half2 w2,
                                       unsigned a, unsigned b, unsigned c) {
    return __hfma2(w2, u2h(c), __hfma2(w1, u2h(b), __hmul2(w0, u2h(a))));
}

// ---------------- prep: normalize / transpose / scale / topk ----------------
__global__ void prep_kernel(
    const float* __restrict__ e1_0, const float* __restrict__ e1_1, const float* __restrict__ e1_2,
    const float* __restrict__ e2_0, const float* __restrict__ e2_1, const float* __restrict__ e2_2,
    const float* __restrict__ c1_1, const float* __restrict__ c1_2,
    const float* __restrict__ c2_1, const float* __restrict__ c2_2,
    const float* __restrict__ a_1,  const float* __restrict__ a_2,
    const float* __restrict__ b_1,  const float* __restrict__ b_2,
    const float* __restrict__ link0, const float* __restrict__ link1)
{
    __shared__ float sp[4];
    int bid = blockIdx.x;
    int d = threadIdx.x;   // 0..127

    if (bid < 3072) {
        // L2-normalize one embedding row
        int which = bid / 1536;            // 0 = emb1, 1 = emb2
        int t = bid % 1536;
        int l = t / B, r = t % B;
        const float* src = (which == 0)
            ? (l == 0 ? e1_0 : (l == 1 ? e1_1 : e1_2))
            : (l == 0 ? e2_0 : (l == 1 ? e2_1 : e2_2));
        float x = src[r * D + d];
        float ss = x * x;
        #pragma unroll
        for (int o = 16; o; o >>= 1) ss += __shfl_xor_sync(0xffffffffu, ss, o);
        if ((d & 31) == 0) sp[d >> 5] = ss;
        __syncthreads();
        float tot = sp[0] + sp[1] + sp[2] + sp[3];
        float inv = 1.0f / fmaxf(sqrtf(tot), 1e-12f);
        float v = x * inv;
        if (which == 0) g_e1n[l][r][d]   = v;
        else            g_e2nTh[l][d][r] = __float2half_rn(v);
    } else if (bid < 4096) {
        // c1p = cert1 * 0.5*alpha
        int t = bid - 3072;
        int l = t / B, r = t % B;
        const float* c = (l == 0) ? c1_1 : c1_2;
        const float* a = (l == 0) ? a_1  : a_2;
        g_c1p[l][r][d] = c[r * D + d] * (0.5f * a[d]);
    } else if (bid < 5120) {
        // cert2 transpose + fp16
        int t = bid - 4096;
        int l = t / B, r = t % B;
        const float* c = (l == 0) ? c2_1 : c2_2;
        g_c2Th[l][d][r] = __float2half_rn(c[r * D + d]);
    } else if (bid == 5120) {
        g_bp[0][d] = 0.5f * b_1[d];
        g_bp[1][d] = 0.5f * b_2[d];
    } else {
        // top-3 per column + column normalization; bid 5121 -> link0, 5122 -> link1
        int m = bid - 5121;
        int e = d;
        const float* L = m ? link1 : link0;
        float v0 = -1e30f, v1 = -1e30f, v2 = -1e30f;
        int   i0 = 0, i1 = 0, i2 = 0;
        for (int r = 0; r < D; ++r) {
            float w = L[r * D + e];     // column e, row r
            if (w > v0)      { v2 = v1; i2 = i1; v1 = v0; i1 = i0; v0 = w; i0 = r; }
            else if (w > v1) { v2 = v1; i2 = i1; v1 = w;  i1 = r; }
            else if (w > v2) { v2 = w;  i2 = r; }
        }
        float inv = 1.0f / (v0 + v1 + v2 + 1e-8f);
        unsigned h0 = (unsigned)__half_as_ushort(__float2half_rn(v0 * inv));
        unsigned h1 = (unsigned)__half_as_ushort(__float2half_rn(v1 * inv));
        unsigned h2 = (unsigned)__half_as_ushort(__float2half_rn(v2 * inv));
        g_wH[m][e] = make_uint4(h0 * 0x10001u, h1 * 0x10001u, h2 * 0x10001u,
                                (unsigned)i0 | ((unsigned)i1 << 8) | ((unsigned)i2 << 16));
    }
}

// ---------------- fused similarity kernel ----------------
// block = (8 j-octs, 64 channel-pairs) = 512 threads, 2 blocks/SM;
// each thread: 2 channels x 8 j (uint4 = 8 halves). All nh gathers/stores are
// LDS.128 where each 8-lane group covers one full 128B row -> conflict-free.
// e2/c2 LDG.128 prefetched one layer ahead. Math in half2 incl. tanh.f16x2.
__global__ __launch_bounds__(512, 2) void avsl_main_kernel(float* __restrict__ out)
{
    __shared__ union {
        __half nh[D][JT];        // 16 KB, dead after layer-2 gathers
        float4 sRed[16][16];     // 4 KB, aliased for the final reduction
    } u;
    __shared__ uint4    sW[2][D];    // 4 KB
    __shared__ unsigned sIh[5][D];   // 2.5 KB: broadcast-half2 of e1n l0..2, c1p l1..2
    __shared__ unsigned sBPh[2][D];  // 1 KB:  broadcast-half2 of bp

    const int q   = threadIdx.x;     // 0..7  (j-oct)
    const int g   = threadIdx.y;     // 0..63 (channel pair)
    const int tid = g * 8 + q;
    const int jj  = blockIdx.x * JT + q * 8;
    const int i   = blockIdx.y;

    // stage W + bp (one writer per word)
    if (tid < 2 * D) {
        ((uint4*)sW)[tid] = ((const uint4*)g_wH)[tid];
        ((unsigned*)sBPh)[tid] = h2u(__float2half2_rn(((const float*)g_bp)[tid]));
    }
    // stage i-side constants as broadcast half2: 5 segments x D
    for (int t = tid; t < 5 * D; t += 512) {
        int seg = t >> 7, d = t & 127;
        float v;
        if (seg == 0)      v = g_e1n[0][i][d];
        else if (seg < 3)  v = g_e1n[seg][i][d];
        else               v = g_c1p[seg - 3][i][d];
        sIh[seg][d] = h2u(__float2half2_rn(v));
    }
    __syncthreads();

    const __half2 H05 = __float2half2_rn(0.5f);
    const int e0 = g * 2, e1c = g * 2 + 1;

    // ---- layer 0 (also prefetch layer-1 LDGs) ----
    {
        uint4 ea = *(const uint4*)&g_e2nTh[0][e0][jj];
        uint4 eb = *(const uint4*)&g_e2nTh[0][e1c][jj];
        __half2 h0 = u2h(sIh[0][e0]), h1 = u2h(sIh[0][e1c]);
        uint4 ra, rb;
        __half2 v;
        v = __hsub2(h0, u2h(ea.x)); ra.x = h2u(__hmul2(v, v));
        v = __hsub2(h0, u2h(ea.y)); ra.y = h2u(__hmul2(v, v));
        v = __hsub2(h0, u2h(ea.z)); ra.z = h2u(__hmul2(v, v));
        v = __hsub2(h0, u2h(ea.w)); ra.w = h2u(__hmul2(v, v));
        v = __hsub2(h1, u2h(eb.x)); rb.x = h2u(__hmul2(v, v));
        v = __hsub2(h1, u2h(eb.y)); rb.y = h2u(__hmul2(v, v));
        v = __hsub2(h1, u2h(eb.z)); rb.z = h2u(__hmul2(v, v));
        v = __hsub2(h1, u2h(eb.w)); rb.w = h2u(__hmul2(v, v));
        *(uint4*)&u.nh[e0][q * 8]  = ra;
        *(uint4*)&u.nh[e1c][q * 8] = rb;
    }
    uint4 e2p[2], c2p[2];
    e2p[0] = *(const uint4*)&g_e2nTh[1][e0][jj];
    e2p[1] = *(const uint4*)&g_e2nTh[1][e1c][jj];
    c2p[0] = *(const uint4*)&g_c2Th[0][e0][jj];
    c2p[1] = *(const uint4*)&g_c2Th[0][e1c][jj];
    __syncthreads();

    // ---- layer 1 ----
    uint4 tnh[2];
    #pragma unroll
    for (int k = 0; k < 2; ++k) {
        const int e = g * 2 + k;
        const uint4 W = sW[0][e];
        const __half2 w0 = u2h(W.x), w1 = u2h(W.y), w2 = u2h(W.z);
        const int o0 = (int)(W.w & 255u) * 8;
        const int o1 = (int)((W.w >> 8) & 255u) * 8;
        const int o2 = (int)((W.w >> 16) & 255u) * 8;
        const uint4* nb = (const uint4*)u.nh;
        uint4 r0 = nb[o0 + q], r1 = nb[o1 + q], r2 = nb[o2 + q];
        __half2 ha = u2h(sIh[1][e]);
        __half2 cp = u2h(sIh[3][e]);
        __half2 bp = u2h(sBPh[0][e]);
        uint4 res;
        res.x = h2u(blend2(ha, u2h(e2p[k].x), cp, u2h(c2p[k].x), bp,
                           ws3(w0, w1, w2, r0.x, r1.x, r2.x), H05));
        res.y = h2u(blend2(ha, u2h(e2p[k].y), cp, u2h(c2p[k].y), bp,
                           ws3(w0, w1, w2, r0.y, r1.y, r2.y), H05));
        res.z = h2u(blend2(ha, u2h(e2p[k].z), cp, u2h(c2p[k].z), bp,
                           ws3(w0, w1, w2, r0.z, r1.z, r2.z), H05));
        res.w = h2u(blend2(ha, u2h(e2p[k].w), cp, u2h(c2p[k].w), bp,
                           ws3(w0, w1, w2, r0.w, r1.w, r2.w), H05));
        tnh[k] = res;
    }
    // prefetch layer-2 LDGs
    e2p[0] = *(const uint4*)&g_e2nTh[2][e0][jj];
    e2p[1] = *(const uint4*)&g_e2nTh[2][e1c][jj];
    c2p[0] = *(const uint4*)&g_c2Th[1][e0][jj];
    c2p[1] = *(const uint4*)&g_c2Th[1][e1c][jj];
    __syncthreads();   // all layer-1 gathers done before overwrite
    *(uint4*)&u.nh[e0][q * 8]  = tnh[0];
    *(uint4*)&u.nh[e1c][q * 8] = tnh[1];
    __syncthreads();

    // ---- layer 2 + channel accumulation (fp32 acc) ----
    float4 a0 = make_float4(0.f, 0.f, 0.f, 0.f);
    float4 a1 = make_float4(0.f, 0.f, 0.f, 0.f);
    #pragma unroll
    for (int k = 0; k < 2; ++k) {
        const int e = g * 2 + k;
        const uint4 W = sW[1][e];
        const __half2 w0 = u2h(W.x), w1 = u2h(W.y), w2 = u2h(W.z);
        const int o0 = (int)(W.w & 255u) * 8;
        const int o1 = (int)((W.w >> 8) & 255u) * 8;
        const int o2 = (int)((W.w >> 16) & 255u) * 8;
        const uint4* nb = (const uint4*)u.nh;
        uint4 r0 = nb[o0 + q], r1 = nb[o1 + q], r2 = nb[o2 + q];
        __half2 ha = u2h(sIh[2][e]);
        __half2 cp = u2h(sIh[4][e]);
        __half2 bp = u2h(sBPh[1][e]);
        __half2 rA = blend2(ha, u2h(e2p[k].x), cp, u2h(c2p[k].x), bp,
                            ws3(w0, w1, w2, r0.x, r1.x, r2.x), H05);
        __half2 rB = blend2(ha, u2h(e2p[k].y), cp, u2h(c2p[k].y), bp,
                            ws3(w0, w1, w2, r0.y, r1.y, r2.y), H05);
        __half2 rC = blend2(ha, u2h(e2p[k].z), cp, u2h(c2p[k].z), bp,
                            ws3(w0, w1, w2, r0.z, r1.z, r2.z), H05);
        __half2 rD = blend2(ha, u2h(e2p[k].w), cp, u2h(c2p[k].w), bp,
                            ws3(w0, w1, w2, r0.w, r1.w, r2.w), H05);
        float2 fA = __half22float2(rA), fB = __half22float2(rB);
        float2 fC = __half22float2(rC), fD = __half22float2(rD);
        a0.x += fA.x; a0.y += fA.y; a0.z += fB.x; a0.w += fB.y;
        a1.x += fC.x; a1.y += fC.y; a1.z += fD.x; a1.w += fD.y;
    }
    __syncthreads();   // nh dead from here: sRed alias is safe

    // fold the 4 channel-pair groups sharing a warp (8-lane groups)
    a0.x += __shfl_down_sync(0xffffffffu, a0.x, 16);
    a0.y += __shfl_down_sync(0xffffffffu, a0.y, 16);
    a0.z += __shfl_down_sync(0xffffffffu, a0.z, 16);
    a0.w += __shfl_down_sync(0xffffffffu, a0.w, 16);
    a1.x += __shfl_down_sync(0xffffffffu, a1.x, 16);
    a1.y += __shfl_down_sync(0xffffffffu, a1.y, 16);
    a1.z += __shfl_down_sync(0xffffffffu, a1.z, 16);
    a1.w += __shfl_down_sync(0xffffffffu, a1.w, 16);
    a0.x += __shfl_down_sync(0xffffffffu, a0.x, 8);
    a0.y += __shfl_down_sync(0xffffffffu, a0.y, 8);
    a0.z += __shfl_down_sync(0xffffffffu, a0.z, 8);
    a0.w += __shfl_down_sync(0xffffffffu, a0.w, 8);
    a1.x += __shfl_down_sync(0xffffffffu, a1.x, 8);
    a1.y += __shfl_down_sync(0xffffffffu, a1.y, 8);
    a1.z += __shfl_down_sync(0xffffffffu, a1.z, 8);
    a1.w += __shfl_down_sync(0xffffffffu, a1.w, 8);
    const int w = tid >> 5, lane = tid & 31;
    if (lane < 8) {
        u.sRed[w][lane * 2]     = a0;
        u.sRed[w][lane * 2 + 1] = a1;
    }
    __syncthreads();
    if (tid < 16) {   // slot = tid: q = tid>>1, half = tid&1
        float4 tot = make_float4(0.f, 0.f, 0.f, 0.f);
        #pragma unroll
        for (int ww = 0; ww < 16; ++ww) {
            float4 t = u.sRed[ww][tid];
            tot.x += t.x; tot.y += t.y; tot.z += t.z; tot.w += t.w;
        }
        *(float4*)&out[i * B + blockIdx.x * JT + tid * 4] = tot;
    }
}

// ---------------- launch ----------------
extern "C" void kernel_launch(void* const* d_in, const int* in_sizes, int n_in,
                              void* d_out, int out_size)
{
    (void)n_in; (void)out_size;

    const float *e1_0, *e1_1, *e1_2, *e2_0, *e2_1, *e2_2;
    const float *c1_1, *c1_2, *c2_1, *c2_2;
    const float *a_1, *a_2, *b_1, *b_2;
    const float *link0, *link1;

    // Detect input ordering at runtime via element counts (see round-1 note).
    if (in_sizes[4] == 128) {
        // dict insertion order (interleaved per layer)
        e1_0 = (const float*)d_in[0];   e2_0 = (const float*)d_in[1];
        e1_1 = (const float*)d_in[6];   e2_1 = (const float*)d_in[7];
        e1_2 = (const float*)d_in[12];  e2_2 = (const float*)d_in[13];
        c1_1 = (const float*)d_in[8];   c2_1 = (const float*)d_in[9];
        c1_2 = (const float*)d_in[14];  c2_2 = (const float*)d_in[15];
        a_1  = (const float*)d_in[10];  b_1  = (const float*)d_in[11];
        a_2  = (const float*)d_in[16];  b_2  = (const float*)d_in[17];
        link0 = (const float*)d_in[18]; link1 = (const float*)d_in[19];
    } else {
        // function-signature order (grouped)
        e1_0 = (const float*)d_in[0];   e1_1 = (const float*)d_in[1];
        e1_2 = (const float*)d_in[2];
        e2_0 = (const float*)d_in[3];   e2_1 = (const float*)d_in[4];
        e2_2 = (const float*)d_in[5];
        c1_1 = (const float*)d_in[7];   c1_2 = (const float*)d_in[8];
        c2_1 = (const float*)d_in[10];  c2_2 = (const float*)d_in[11];
        a_1  = (const float*)d_in[13];  a_2  = (const float*)d_in[14];
        b_1  = (const float*)d_in[16];  b_2  = (const float*)d_in[17];
        link0 = (const float*)d_in[18]; link1 = (const float*)d_in[19];
    }

    prep_kernel<<<5123, 128>>>(e1_0, e1_1, e1_2, e2_0, e2_1, e2_2,
                               c1_1, c1_2, c2_1, c2_2, a_1, a_2, b_1, b_2,
                               link0, link1);

    dim3 grid(B / JT, B);   // (8, 512)
    dim3 blk(8, 64);
    avsl_main_kernel<<<grid, blk>>>((float*)d_out);
}

// round 9
// speedup vs baseline: 1.3224x; 1.0650x over previous
#include <cuda_runtime.h>
#include <cuda_fp16.h>

#define B 512
#define D 128
#define JT 64            // j per block

// ---------------- device scratch (no allocation allowed) ----------------
__device__ float  g_e1n[3][B][D];     // normalized emb1, row-major [l][i][d]
__device__ __half g_e2nTh[3][D][B];   // normalized emb2, fp16, transposed [l][d][j]
__device__ float  g_c1p[2][B][D];     // cert1_{1,2} * 0.5*alpha_{1,2}
__device__ __half g_c2Th[2][D][B];    // cert2_{1,2}, fp16, transposed [l][d][j]
__device__ float  g_bp[2][D];         // 0.5*beta_{1,2}
__device__ uint4  g_wH[2][D];         // .x/.y/.z = broadcast half2 of w0..w2, .w = packed idx

__device__ __forceinline__ __half2 u2h(unsigned x) {
    __half2 h; *(unsigned*)&h = x; return h;
}
__device__ __forceinline__ unsigned h2u(__half2 h) {
    return *(unsigned*)&h;
}
__device__ __forceinline__ __half2 tanh2(__half2 x) {
    unsigned xi = h2u(x), yo;
    asm("tanh.approx.f16x2 %0, %1;" : "=r"(yo) : "r"(xi));
    return u2h(yo);
}
// r = s + P*(n-s),  n = (a-e2)^2,  P = 0.5*tanh(cp*c2+bp)+0.5   (all half2)
__device__ __forceinline__ __half2 blend2(__half2 ha, __half2 e2, __half2 cp,
                                          __half2 c2, __half2 bp, __half2 s,
                                          __half2 H05) {
    __half2 v = __hsub2(ha, e2);
    __half2 n = __hmul2(v, v);
    __half2 P = __hfma2(H05, tanh2(__hfma2(cp, c2, bp)), H05);
    return __hfma2(P, __hsub2(n, s), s);
}
// 3-term weighted sum of gathered half2s
__device__ __forceinline__ __half2 ws3(__half2 w0, __half2 w1, __half2 w2,
                                       unsigned a, unsigned b, unsigned c) {
    return __hfma2(w2, u2h(c), __hfma2(w1, u2h(b), __hmul2(w0, u2h(a))));
}

// ---------------- prep: normalize / transpose / scale / topk ----------------
__global__ void prep_kernel(
    const float* __restrict__ e1_0, const float* __restrict__ e1_1, const float* __restrict__ e1_2,
    const float* __restrict__ e2_0, const float* __restrict__ e2_1, const float* __restrict__ e2_2,
    const float* __restrict__ c1_1, const float* __restrict__ c1_2,
    const float* __restrict__ c2_1, const float* __restrict__ c2_2,
    const float* __restrict__ a_1,  const float* __restrict__ a_2,
    const float* __restrict__ b_1,  const float* __restrict__ b_2,
    const float* __restrict__ link0, const float* __restrict__ link1)
{
    __shared__ float sp[4];
    int bid = blockIdx.x;
    int d = threadIdx.x;   // 0..127

    if (bid < 3072) {
        // L2-normalize one embedding row
        int which = bid / 1536;            // 0 = emb1, 1 = emb2
        int t = bid % 1536;
        int l = t / B, r = t % B;
        const float* src = (which == 0)
            ? (l == 0 ? e1_0 : (l == 1 ? e1_1 : e1_2))
            : (l == 0 ? e2_0 : (l == 1 ? e2_1 : e2_2));
        float x = src[r * D + d];
        float ss = x * x;
        #pragma unroll
        for (int o = 16; o; o >>= 1) ss += __shfl_xor_sync(0xffffffffu, ss, o);
        if ((d & 31) == 0) sp[d >> 5] = ss;
        __syncthreads();
        float tot = sp[0] + sp[1] + sp[2] + sp[3];
        float inv = 1.0f / fmaxf(sqrtf(tot), 1e-12f);
        float v = x * inv;
        if (which == 0) g_e1n[l][r][d]   = v;
        else            g_e2nTh[l][d][r] = __float2half_rn(v);
    } else if (bid < 4096) {
        // c1p = cert1 * 0.5*alpha
        int t = bid - 3072;
        int l = t / B, r = t % B;
        const float* c = (l == 0) ? c1_1 : c1_2;
        const float* a = (l == 0) ? a_1  : a_2;
        g_c1p[l][r][d] = c[r * D + d] * (0.5f * a[d]);
    } else if (bid < 5120) {
        // cert2 transpose + fp16
        int t = bid - 4096;
        int l = t / B, r = t % B;
        const float* c = (l == 0) ? c2_1 : c2_2;
        g_c2Th[l][d][r] = __float2half_rn(c[r * D + d]);
    } else if (bid == 5120) {
        g_bp[0][d] = 0.5f * b_1[d];
        g_bp[1][d] = 0.5f * b_2[d];
    } else {
        // top-3 per column + column normalization; bid 5121 -> link0, 5122 -> link1
        int m = bid - 5121;
        int e = d;
        const float* L = m ? link1 : link0;
        float v0 = -1e30f, v1 = -1e30f, v2 = -1e30f;
        int   i0 = 0, i1 = 0, i2 = 0;
        for (int r = 0; r < D; ++r) {
            float w = L[r * D + e];     // column e, row r
            if (w > v0)      { v2 = v1; i2 = i1; v1 = v0; i1 = i0; v0 = w; i0 = r; }
            else if (w > v1) { v2 = v1; i2 = i1; v1 = w;  i1 = r; }
            else if (w > v2) { v2 = w;  i2 = r; }
        }
        float inv = 1.0f / (v0 + v1 + v2 + 1e-8f);
        unsigned h0 = (unsigned)__half_as_ushort(__float2half_rn(v0 * inv));
        unsigned h1 = (unsigned)__half_as_ushort(__float2half_rn(v1 * inv));
        unsigned h2 = (unsigned)__half_as_ushort(__float2half_rn(v2 * inv));
        g_wH[m][e] = make_uint4(h0 * 0x10001u, h1 * 0x10001u, h2 * 0x10001u,
                                (unsigned)i0 | ((unsigned)i1 << 8) | ((unsigned)i2 << 16));
    }
}

// ---------------- fused similarity kernel ----------------
// block = (8 j-octs, 64 channel-pairs) = 512 threads, 3 blocks/SM;
// each thread: 2 channels x 8 j (uint4 = 8 halves). Double-buffered nh
// (layer1 reads A, writes B) removes the gather/overwrite barrier and the
// cross-barrier result registers. All nh accesses LDS.128 conflict-free
// (each 8-lane group covers one full 128B row). Math in half2 incl tanh.f16x2.
__global__ __launch_bounds__(512, 3) void avsl_main_kernel(float* __restrict__ out)
{
    __shared__ union {
        struct { __half A[D][JT]; __half Bb[D][JT]; } nh;  // 32 KB
        float4 sRed[16][16];     // 4 KB, aliased over nh.A (dead at reduction)
    } u;
    __shared__ uint4    sW[2][D];    // 4 KB
    __shared__ unsigned sIh[5][D];   // 2.5 KB: broadcast-half2 of e1n l0..2, c1p l1..2
    __shared__ unsigned sBPh[2][D];  // 1 KB:  broadcast-half2 of bp

    const int q   = threadIdx.x;     // 0..7  (j-oct)
    const int g   = threadIdx.y;     // 0..63 (channel pair)
    const int tid = g * 8 + q;
    const int jj  = blockIdx.x * JT + q * 8;
    const int i   = blockIdx.y;

    // stage W + bp (one writer per word)
    if (tid < 2 * D) {
        ((uint4*)sW)[tid] = ((const uint4*)g_wH)[tid];
        ((unsigned*)sBPh)[tid] = h2u(__float2half2_rn(((const float*)g_bp)[tid]));
    }
    // stage i-side constants as broadcast half2: 5 segments x D
    for (int t = tid; t < 5 * D; t += 512) {
        int seg = t >> 7, d = t & 127;
        float v;
        if (seg == 0)      v = g_e1n[0][i][d];
        else if (seg < 3)  v = g_e1n[seg][i][d];
        else               v = g_c1p[seg - 3][i][d];
        sIh[seg][d] = h2u(__float2half2_rn(v));
    }
    __syncthreads();   // (1)

    const __half2 H05 = __float2half2_rn(0.5f);
    const int e0 = g * 2, e1c = g * 2 + 1;

    // ---- layer 0 -> nh.A ----
    {
        uint4 ea = *(const uint4*)&g_e2nTh[0][e0][jj];
        uint4 eb = *(const uint4*)&g_e2nTh[0][e1c][jj];
        __half2 h0 = u2h(sIh[0][e0]), h1 = u2h(sIh[0][e1c]);
        uint4 ra, rb;
        __half2 v;
        v = __hsub2(h0, u2h(ea.x)); ra.x = h2u(__hmul2(v, v));
        v = __hsub2(h0, u2h(ea.y)); ra.y = h2u(__hmul2(v, v));
        v = __hsub2(h0, u2h(ea.z)); ra.z = h2u(__hmul2(v, v));
        v = __hsub2(h0, u2h(ea.w)); ra.w = h2u(__hmul2(v, v));
        v = __hsub2(h1, u2h(eb.x)); rb.x = h2u(__hmul2(v, v));
        v = __hsub2(h1, u2h(eb.y)); rb.y = h2u(__hmul2(v, v));
        v = __hsub2(h1, u2h(eb.z)); rb.z = h2u(__hmul2(v, v));
        v = __hsub2(h1, u2h(eb.w)); rb.w = h2u(__hmul2(v, v));
        *(uint4*)&u.nh.A[e0][q * 8]  = ra;
        *(uint4*)&u.nh.A[e1c][q * 8] = rb;
    }
    __syncthreads();   // (2)

    // ---- layer 1: gather nh.A -> write nh.B (no extra barrier needed) ----
    #pragma unroll
    for (int k = 0; k < 2; ++k) {
        const int e = g * 2 + k;
        const uint4 W = sW[0][e];
        const __half2 w0 = u2h(W.x), w1 = u2h(W.y), w2 = u2h(W.z);
        const int o0 = (int)(W.w & 255u) * 8;
        const int o1 = (int)((W.w >> 8) & 255u) * 8;
        const int o2 = (int)((W.w >> 16) & 255u) * 8;
        const uint4* nb = (const uint4*)u.nh.A;
        uint4 r0 = nb[o0 + q], r1 = nb[o1 + q], r2 = nb[o2 + q];
        uint4 e2u = *(const uint4*)&g_e2nTh[1][e][jj];
        uint4 c2u = *(const uint4*)&g_c2Th[0][e][jj];
        __half2 ha = u2h(sIh[1][e]);
        __half2 cp = u2h(sIh[3][e]);
        __half2 bp = u2h(sBPh[0][e]);
        uint4 res;
        res.x = h2u(blend2(ha, u2h(e2u.x), cp, u2h(c2u.x), bp,
                           ws3(w0, w1, w2, r0.x, r1.x, r2.x), H05));
        res.y = h2u(blend2(ha, u2h(e2u.y), cp, u2h(c2u.y), bp,
                           ws3(w0, w1, w2, r0.y, r1.y, r2.y), H05));
        res.z = h2u(blend2(ha, u2h(e2u.z), cp, u2h(c2u.z), bp,
                           ws3(w0, w1, w2, r0.z, r1.z, r2.z), H05));
        res.w = h2u(blend2(ha, u2h(e2u.w), cp, u2h(c2u.w), bp,
                           ws3(w0, w1, w2, r0.w, r1.w, r2.w), H05));
        *(uint4*)&u.nh.Bb[e][q * 8] = res;
    }
    __syncthreads();   // (3)

    // ---- layer 2: gather nh.B + channel accumulation (fp32 acc) ----
    float4 a0 = make_float4(0.f, 0.f, 0.f, 0.f);
    float4 a1 = make_float4(0.f, 0.f, 0.f, 0.f);
    #pragma unroll
    for (int k = 0; k < 2; ++k) {
        const int e = g * 2 + k;
        const uint4 W = sW[1][e];
        const __half2 w0 = u2h(W.x), w1 = u2h(W.y), w2 = u2h(W.z);
        const int o0 = (int)(W.w & 255u) * 8;
        const int o1 = (int)((W.w >> 8) & 255u) * 8;
        const int o2 = (int)((W.w >> 16) & 255u) * 8;
        const uint4* nb = (const uint4*)u.nh.Bb;
        uint4 r0 = nb[o0 + q], r1 = nb[o1 + q], r2 = nb[o2 + q];
        uint4 e2u = *(const uint4*)&g_e2nTh[2][e][jj];
        uint4 c2u = *(const uint4*)&g_c2Th[1][e][jj];
        __half2 ha = u2h(sIh[2][e]);
        __half2 cp = u2h(sIh[4][e]);
        __half2 bp = u2h(sBPh[1][e]);
        __half2 rA = blend2(ha, u2h(e2u.x), cp, u2h(c2u.x), bp,
                            ws3(w0, w1, w2, r0.x, r1.x, r2.x), H05);
        __half2 rB = blend2(ha, u2h(e2u.y), cp, u2h(c2u.y), bp,
                            ws3(w0, w1, w2, r0.y, r1.y, r2.y), H05);
        __half2 rC = blend2(ha, u2h(e2u.z), cp, u2h(c2u.z), bp,
                            ws3(w0, w1, w2, r0.z, r1.z, r2.z), H05);
        __half2 rD = blend2(ha, u2h(e2u.w), cp, u2h(c2u.w), bp,
                            ws3(w0, w1, w2, r0.w, r1.w, r2.w), H05);
        float2 fA = __half22float2(rA), fB = __half22float2(rB);
        float2 fC = __half22float2(rC), fD = __half22float2(rD);
        a0.x += fA.x; a0.y += fA.y; a0.z += fB.x; a0.w += fB.y;
        a1.x += fC.x; a1.y += fC.y; a1.z += fD.x; a1.w += fD.y;
    }

    // fold the 4 channel-pair groups sharing a warp (8-lane groups)
    a0.x += __shfl_down_sync(0xffffffffu, a0.x, 16);
    a0.y += __shfl_down_sync(0xffffffffu, a0.y, 16);
    a0.z += __shfl_down_sync(0xffffffffu, a0.z, 16);
    a0.w += __shfl_down_sync(0xffffffffu, a0.w, 16);
    a1.x += __shfl_down_sync(0xffffffffu, a1.x, 16);
    a1.y += __shfl_down_sync(0xffffffffu, a1.y, 16);
    a1.z += __shfl_down_sync(0xffffffffu, a1.z, 16);
    a1.w += __shfl_down_sync(0xffffffffu, a1.w, 16);
    a0.x += __shfl_down_sync(0xffffffffu, a0.x, 8);
    a0.y += __shfl_down_sync(0xffffffffu, a0.y, 8);
    a0.z += __shfl_down_sync(0xffffffffu, a0.z, 8);
    a0.w += __shfl_down_sync(0xffffffffu, a0.w, 8);
    a1.x += __shfl_down_sync(0xffffffffu, a1.x, 8);
    a1.y += __shfl_down_sync(0xffffffffu, a1.y, 8);
    a1.z += __shfl_down_sync(0xffffffffu, a1.z, 8);
    a1.w += __shfl_down_sync(0xffffffffu, a1.w, 8);
    __syncthreads();   // (4) — nh.A reads done at (3); safe to alias sRed now
    const int w = tid >> 5, lane = tid & 31;
    if (lane < 8) {
        u.sRed[w][lane * 2]     = a0;
        u.sRed[w][lane * 2 + 1] = a1;
    }
    __syncthreads();   // (5)
    if (tid < 16) {   // slot = tid: q = tid>>1, half = tid&1
        float4 tot = make_float4(0.f, 0.f, 0.f, 0.f);
        #pragma unroll
        for (int ww = 0; ww < 16; ++ww) {
            float4 t = u.sRed[ww][tid];
            tot.x += t.x; tot.y += t.y; tot.z += t.z; tot.w += t.w;
        }
        *(float4*)&out[i * B + blockIdx.x * JT + tid * 4] = tot;
    }
}

// ---------------- launch ----------------
extern "C" void kernel_launch(void* const* d_in, const int* in_sizes, int n_in,
                              void* d_out, int out_size)
{
    (void)n_in; (void)out_size;

    const float *e1_0, *e1_1, *e1_2, *e2_0, *e2_1, *e2_2;
    const float *c1_1, *c1_2, *c2_1, *c2_2;
    const float *a_1, *a_2, *b_1, *b_2;
    const float *link0, *link1;

    // Detect input ordering at runtime via element counts (see round-1 note).
    if (in_sizes[4] == 128) {
        // dict insertion order (interleaved per layer)
        e1_0 = (const float*)d_in[0];   e2_0 = (const float*)d_in[1];
        e1_1 = (const float*)d_in[6];   e2_1 = (const float*)d_in[7];
        e1_2 = (const float*)d_in[12];  e2_2 = (const float*)d_in[13];
        c1_1 = (const float*)d_in[8];   c2_1 = (const float*)d_in[9];
        c1_2 = (const float*)d_in[14];  c2_2 = (const float*)d_in[15];
        a_1  = (const float*)d_in[10];  b_1  = (const float*)d_in[11];
        a_2  = (const float*)d_in[16];  b_2  = (const float*)d_in[17];
        link0 = (const float*)d_in[18]; link1 = (const float*)d_in[19];
    } else {
        // function-signature order (grouped)
        e1_0 = (const float*)d_in[0];   e1_1 = (const float*)d_in[1];
        e1_2 = (const float*)d_in[2];
        e2_0 = (const float*)d_in[3];   e2_1 = (const float*)d_in[4];
        e2_2 = (const float*)d_in[5];
        c1_1 = (const float*)d_in[7];   c1_2 = (const float*)d_in[8];
        c2_1 = (const float*)d_in[10];  c2_2 = (const float*)d_in[11];
        a_1  = (const float*)d_in[13];  a_2  = (const float*)d_in[14];
        b_1  = (const float*)d_in[16];  b_2  = (const float*)d_in[17];
        link0 = (const float*)d_in[18]; link1 = (const float*)d_in[19];
    }

    prep_kernel<<<5123, 128>>>(e1_0, e1_1, e1_2, e2_0, e2_1, e2_2,
                               c1_1, c1_2, c2_1, c2_2, a_1, a_2, b_1, b_2,
                               link0, link1);

    dim3 grid(B / JT, B);   // (8, 512)
    dim3 blk(8, 64);
    avsl_main_kernel<<<grid, blk>>>((float*)d_out);
}

// round 10
// speedup vs baseline: 1.3985x; 1.0575x over previous
#include <cuda_runtime.h>
#include <cuda_fp16.h>

#define B 512
#define D 128
#define JT 64            // j per block

// ---------------- device scratch (no allocation allowed) ----------------
__device__ float  g_e1n[3][B][D];     // normalized emb1, row-major [l][i][d]
__device__ __half g_e2nTh[3][D][B];   // normalized emb2, fp16, transposed [l][d][j]
__device__ float  g_c1p[2][B][D];     // cert1_{1,2} * 0.5*alpha_{1,2}
__device__ __half g_c2Th[2][D][B];    // cert2_{1,2}, fp16, transposed [l][d][j]
__device__ float  g_bp[2][D];         // 0.5*beta_{1,2}
__device__ uint4  g_wH[2][D];         // .x/.y/.z = broadcast half2 of w0..w2, .w = packed idx

__device__ __forceinline__ __half2 u2h(unsigned x) {
    __half2 h; *(unsigned*)&h = x; return h;
}
__device__ __forceinline__ unsigned h2u(__half2 h) {
    return *(unsigned*)&h;
}
__device__ __forceinline__ __half2 tanh2(__half2 x) {
    unsigned xi = h2u(x), yo;
    asm("tanh.approx.f16x2 %0, %1;" : "=r"(yo) : "r"(xi));
    return u2h(yo);
}
// r = s + P*(n-s),  n = (a-e2)^2,  P = 0.5*tanh(cp*c2+bp)+0.5   (all half2)
__device__ __forceinline__ __half2 blend2(__half2 ha, __half2 e2, __half2 cp,
                                          __half2 c2, __half2 bp, __half2 s,
                                          __half2 H05) {
    __half2 v = __hsub2(ha, e2);
    __half2 n = __hmul2(v, v);
    __half2 P = __hfma2(H05, tanh2(__hfma2(cp, c2, bp)), H05);
    return __hfma2(P, __hsub2(n, s), s);
}
// 3-term weighted sum of gathered half2s
__device__ __forceinline__ __half2 ws3(__half2 w0, __half2 w1, __half2 w2,
                                       unsigned a, unsigned b, unsigned c) {
    return __hfma2(w2, u2h(c), __hfma2(w1, u2h(b), __hmul2(w0, u2h(a))));
}

// ---------------- prep v2: coalesced tiled transposes + warp-per-row norms --
// grid = 299 blocks x 256 threads:
//   [0,24)    e2 normalize+transpose tiles (3 l x 8 row-tiles of 64)
//   [24,40)   c2 transpose tiles (2 l x 8)
//   [40,232)  e1 normalize rows (warp per row, 8 rows/block)
//   [232,296) c1p elementwise
//   296       bp
//   297,298   topk link0/link1
__global__ __launch_bounds__(256) void prep_kernel(
    const float* __restrict__ e1_0, const float* __restrict__ e1_1, const float* __restrict__ e1_2,
    const float* __restrict__ e2_0, const float* __restrict__ e2_1, const float* __restrict__ e2_2,
    const float* __restrict__ c1_1, const float* __restrict__ c1_2,
    const float* __restrict__ c2_1, const float* __restrict__ c2_2,
    const float* __restrict__ a_1,  const float* __restrict__ a_2,
    const float* __restrict__ b_1,  const float* __restrict__ b_2,
    const float* __restrict__ link0, const float* __restrict__ link1)
{
    __shared__ float sm[64][129];   // padded: conflict-free column reads
    __shared__ float part[4][64];
    __shared__ float sInv[64];

    const int bid = blockIdx.x;
    const int t   = threadIdx.x;    // 0..255

    if (bid < 40) {
        // ---- tiled transpose (e2: with L2-normalization; c2: plain) ----
        const bool isE = bid < 24;
        const int t2 = isE ? bid : bid - 24;
        const int l = t2 >> 3, rt = t2 & 7;
        const float* src = isE ? (l == 0 ? e2_0 : (l == 1 ? e2_1 : e2_2))
                               : (l == 0 ? c2_1 : c2_2);
        const int r0 = rt * 64;
        // coalesced load of 64x128 tile
        for (int idx = t; idx < 64 * 128; idx += 256) {
            int rr = idx >> 7, c = idx & 127;
            sm[rr][c] = src[(r0 + rr) * D + c];
        }
        __syncthreads();
        if (isE) {
            int qd = t >> 6, rr = t & 63;
            float ss = 0.f;
            #pragma unroll 8
            for (int c = qd * 32; c < qd * 32 + 32; ++c) {
                float x = sm[rr][c]; ss += x * x;
            }
            part[qd][rr] = ss;
            __syncthreads();
            if (t < 64) {
                float tot = part[0][t] + part[1][t] + part[2][t] + part[3][t];
                sInv[t] = 1.0f / fmaxf(sqrtf(tot), 1e-12f);
            }
        } else {
            if (t < 64) sInv[t] = 1.0f;
        }
        __syncthreads();
        __half (*dst)[B] = isE ? g_e2nTh[l] : g_c2Th[l];
        // transposed write: consecutive threads -> consecutive r (coalesced)
        for (int idx = t; idx < 64 * 128; idx += 256) {
            int d2 = idx >> 6, rr = idx & 63;
            dst[d2][r0 + rr] = __float2half_rn(sm[rr][d2] * sInv[rr]);
        }
    } else if (bid < 232) {
        // ---- e1 normalize: warp per row, float4 per lane ----
        int rid = (bid - 40) * 8 + (t >> 5);        // 0..1535
        int l = rid / 512, r = rid % 512;
        const float* src = (l == 0) ? e1_0 : (l == 1 ? e1_1 : e1_2);
        int lane = t & 31;
        float4 x = *(const float4*)&src[r * D + lane * 4];
        float ss = x.x * x.x + x.y * x.y + x.z * x.z + x.w * x.w;
        #pragma unroll
        for (int o = 16; o; o >>= 1) ss += __shfl_xor_sync(0xffffffffu, ss, o);
        float inv = 1.0f / fmaxf(sqrtf(ss), 1e-12f);
        float4 v = make_float4(x.x * inv, x.y * inv, x.z * inv, x.w * inv);
        *(float4*)&g_e1n[l][r][lane * 4] = v;
    } else if (bid < 296) {
        // ---- c1p = cert1 * 0.5*alpha, elementwise coalesced ----
        int base = (bid - 232) * 2048;
        #pragma unroll
        for (int k = 0; k < 8; ++k) {
            int idx = base + k * 256 + t;           // 0..131071
            int l = idx >> 16;
            int rem = idx & 65535;
            int d2 = rem & 127;
            const float* c = l ? c1_2 : c1_1;
            const float* a = l ? a_2  : a_1;
            ((float*)g_c1p[l])[rem] = c[rem] * (0.5f * a[d2]);
        }
    } else if (bid == 296) {
        if (t < 128) {
            g_bp[0][t] = 0.5f * b_1[t];
            g_bp[1][t] = 0.5f * b_2[t];
        }
    } else {
        // ---- top-3 per column + column normalization ----
        int m = bid - 297;
        if (t < 128) {
            int e = t;
            const float* L = m ? link1 : link0;
            float v0 = -1e30f, v1 = -1e30f, v2 = -1e30f;
            int   i0 = 0, i1 = 0, i2 = 0;
            for (int r = 0; r < D; ++r) {
                float w = L[r * D + e];
                if (w > v0)      { v2 = v1; i2 = i1; v1 = v0; i1 = i0; v0 = w; i0 = r; }
                else if (w > v1) { v2 = v1; i2 = i1; v1 = w;  i1 = r; }
                else if (w > v2) { v2 = w;  i2 = r; }
            }
            float inv = 1.0f / (v0 + v1 + v2 + 1e-8f);
            unsigned h0 = (unsigned)__half_as_ushort(__float2half_rn(v0 * inv));
            unsigned h1 = (unsigned)__half_as_ushort(__float2half_rn(v1 * inv));
            unsigned h2 = (unsigned)__half_as_ushort(__float2half_rn(v2 * inv));
            g_wH[m][e] = make_uint4(h0 * 0x10001u, h1 * 0x10001u, h2 * 0x10001u,
                                    (unsigned)i0 | ((unsigned)i1 << 8) | ((unsigned)i2 << 16));
        }
    }
}

// ---------------- fused similarity kernel (unchanged from round 9) ----------
__global__ __launch_bounds__(512, 3) void avsl_main_kernel(float* __restrict__ out)
{
    __shared__ union {
        struct { __half A[D][JT]; __half Bb[D][JT]; } nh;  // 32 KB
        float4 sRed[16][16];     // 4 KB, aliased over nh.A (dead at reduction)
    } u;
    __shared__ uint4    sW[2][D];    // 4 KB
    __shared__ unsigned sIh[5][D];   // 2.5 KB: broadcast-half2 of e1n l0..2, c1p l1..2
    __shared__ unsigned sBPh[2][D];  // 1 KB:  broadcast-half2 of bp

    const int q   = threadIdx.x;     // 0..7  (j-oct)
    const int g   = threadIdx.y;     // 0..63 (channel pair)
    const int tid = g * 8 + q;
    const int jj  = blockIdx.x * JT + q * 8;
    const int i   = blockIdx.y;

    if (tid < 2 * D) {
        ((uint4*)sW)[tid] = ((const uint4*)g_wH)[tid];
        ((unsigned*)sBPh)[tid] = h2u(__float2half2_rn(((const float*)g_bp)[tid]));
    }
    for (int t = tid; t < 5 * D; t += 512) {
        int seg = t >> 7, d = t & 127;
        float v;
        if (seg == 0)      v = g_e1n[0][i][d];
        else if (seg < 3)  v = g_e1n[seg][i][d];
        else               v = g_c1p[seg - 3][i][d];
        sIh[seg][d] = h2u(__float2half2_rn(v));
    }
    __syncthreads();

    const __half2 H05 = __float2half2_rn(0.5f);
    const int e0 = g * 2, e1c = g * 2 + 1;

    // ---- layer 0 -> nh.A ----
    {
        uint4 ea = *(const uint4*)&g_e2nTh[0][e0][jj];
        uint4 eb = *(const uint4*)&g_e2nTh[0][e1c][jj];
        __half2 h0 = u2h(sIh[0][e0]), h1 = u2h(sIh[0][e1c]);
        uint4 ra, rb;
        __half2 v;
        v = __hsub2(h0, u2h(ea.x)); ra.x = h2u(__hmul2(v, v));
        v = __hsub2(h0, u2h(ea.y)); ra.y = h2u(__hmul2(v, v));
        v = __hsub2(h0, u2h(ea.z)); ra.z = h2u(__hmul2(v, v));
        v = __hsub2(h0, u2h(ea.w)); ra.w = h2u(__hmul2(v, v));
        v = __hsub2(h1, u2h(eb.x)); rb.x = h2u(__hmul2(v, v));
        v = __hsub2(h1, u2h(eb.y)); rb.y = h2u(__hmul2(v, v));
        v = __hsub2(h1, u2h(eb.z)); rb.z = h2u(__hmul2(v, v));
        v = __hsub2(h1, u2h(eb.w)); rb.w = h2u(__hmul2(v, v));
        *(uint4*)&u.nh.A[e0][q * 8]  = ra;
        *(uint4*)&u.nh.A[e1c][q * 8] = rb;
    }
    __syncthreads();

    // ---- layer 1: gather nh.A -> write nh.B ----
    #pragma unroll
    for (int k = 0; k < 2; ++k) {
        const int e = g * 2 + k;
        const uint4 W = sW[0][e];
        const __half2 w0 = u2h(W.x), w1 = u2h(W.y), w2 = u2h(W.z);
        const int o0 = (int)(W.w & 255u) * 8;
        const int o1 = (int)((W.w >> 8) & 255u) * 8;
        const int o2 = (int)((W.w >> 16) & 255u) * 8;
        const uint4* nb = (const uint4*)u.nh.A;
        uint4 r0 = nb[o0 + q], r1 = nb[o1 + q], r2 = nb[o2 + q];
        uint4 e2u = *(const uint4*)&g_e2nTh[1][e][jj];
        uint4 c2u = *(const uint4*)&g_c2Th[0][e][jj];
        __half2 ha = u2h(sIh[1][e]);
        __half2 cp = u2h(sIh[3][e]);
        __half2 bp = u2h(sBPh[0][e]);
        uint4 res;
        res.x = h2u(blend2(ha, u2h(e2u.x), cp, u2h(c2u.x), bp,
                           ws3(w0, w1, w2, r0.x, r1.x, r2.x), H05));
        res.y = h2u(blend2(ha, u2h(e2u.y), cp, u2h(c2u.y), bp,
                           ws3(w0, w1, w2, r0.y, r1.y, r2.y), H05));
        res.z = h2u(blend2(ha, u2h(e2u.z), cp, u2h(c2u.z), bp,
                           ws3(w0, w1, w2, r0.z, r1.z, r2.z), H05));
        res.w = h2u(blend2(ha, u2h(e2u.w), cp, u2h(c2u.w), bp,
                           ws3(w0, w1, w2, r0.w, r1.w, r2.w), H05));
        *(uint4*)&u.nh.Bb[e][q * 8] = res;
    }
    __syncthreads();

    // ---- layer 2: gather nh.B + channel accumulation (fp32 acc) ----
    float4 a0 = make_float4(0.f, 0.f, 0.f, 0.f);
    float4 a1 = make_float4(0.f, 0.f, 0.f, 0.f);
    #pragma unroll
    for (int k = 0; k < 2; ++k) {
        const int e = g * 2 + k;
        const uint4 W = sW[1][e];
        const __half2 w0 = u2h(W.x), w1 = u2h(W.y), w2 = u2h(W.z);
        const int o0 = (int)(W.w & 255u) * 8;
        const int o1 = (int)((W.w >> 8) & 255u) * 8;
        const int o2 = (int)((W.w >> 16) & 255u) * 8;
        const uint4* nb = (const uint4*)u.nh.Bb;
        uint4 r0 = nb[o0 + q], r1 = nb[o1 + q], r2 = nb[o2 + q];
        uint4 e2u = *(const uint4*)&g_e2nTh[2][e][jj];
        uint4 c2u = *(const uint4*)&g_c2Th[1][e][jj];
        __half2 ha = u2h(sIh[2][e]);
        __half2 cp = u2h(sIh[4][e]);
        __half2 bp = u2h(sBPh[1][e]);
        __half2 rA = blend2(ha, u2h(e2u.x), cp, u2h(c2u.x), bp,
                            ws3(w0, w1, w2, r0.x, r1.x, r2.x), H05);
        __half2 rB = blend2(ha, u2h(e2u.y), cp, u2h(c2u.y), bp,
                            ws3(w0, w1, w2, r0.y, r1.y, r2.y), H05);
        __half2 rC = blend2(ha, u2h(e2u.z), cp, u2h(c2u.z), bp,
                            ws3(w0, w1, w2, r0.z, r1.z, r2.z), H05);
        __half2 rD = blend2(ha, u2h(e2u.w), cp, u2h(c2u.w), bp,
                            ws3(w0, w1, w2, r0.w, r1.w, r2.w), H05);
        float2 fA = __half22float2(rA), fB = __half22float2(rB);
        float2 fC = __half22float2(rC), fD = __half22float2(rD);
        a0.x += fA.x; a0.y += fA.y; a0.z += fB.x; a0.w += fB.y;
        a1.x += fC.x; a1.y += fC.y; a1.z += fD.x; a1.w += fD.y;
    }

    // fold the 4 channel-pair groups sharing a warp (8-lane groups)
    a0.x += __shfl_down_sync(0xffffffffu, a0.x, 16);
    a0.y += __shfl_down_sync(0xffffffffu, a0.y, 16);
    a0.z += __shfl_down_sync(0xffffffffu, a0.z, 16);
    a0.w += __shfl_down_sync(0xffffffffu, a0.w, 16);
    a1.x += __shfl_down_sync(0xffffffffu, a1.x, 16);
    a1.y += __shfl_down_sync(0xffffffffu, a1.y, 16);
    a1.z += __shfl_down_sync(0xffffffffu, a1.z, 16);
    a1.w += __shfl_down_sync(0xffffffffu, a1.w, 16);
    a0.x += __shfl_down_sync(0xffffffffu, a0.x, 8);
    a0.y += __shfl_down_sync(0xffffffffu, a0.y, 8);
    a0.z += __shfl_down_sync(0xffffffffu, a0.z, 8);
    a0.w += __shfl_down_sync(0xffffffffu, a0.w, 8);
    a1.x += __shfl_down_sync(0xffffffffu, a1.x, 8);
    a1.y += __shfl_down_sync(0xffffffffu, a1.y, 8);
    a1.z += __shfl_down_sync(0xffffffffu, a1.z, 8);
    a1.w += __shfl_down_sync(0xffffffffu, a1.w, 8);
    __syncthreads();
    const int w = tid >> 5, lane = tid & 31;
    if (lane < 8) {
        u.sRed[w][lane * 2]     = a0;
        u.sRed[w][lane * 2 + 1] = a1;
    }
    __syncthreads();
    if (tid < 16) {
        float4 tot = make_float4(0.f, 0.f, 0.f, 0.f);
        #pragma unroll
        for (int ww = 0; ww < 16; ++ww) {
            float4 t = u.sRed[ww][tid];
            tot.x += t.x; tot.y += t.y; tot.z += t.z; tot.w += t.w;
        }
        *(float4*)&out[i * B + blockIdx.x * JT + tid * 4] = tot;
    }
}

// ---------------- launch ----------------
extern "C" void kernel_launch(void* const* d_in, const int* in_sizes, int n_in,
                              void* d_out, int out_size)
{
    (void)n_in; (void)out_size;

    const float *e1_0, *e1_1, *e1_2, *e2_0, *e2_1, *e2_2;
    const float *c1_1, *c1_2, *c2_1, *c2_2;
    const float *a_1, *a_2, *b_1, *b_2;
    const float *link0, *link1;

    // Detect input ordering at runtime via element counts (see round-1 note).
    if (in_sizes[4] == 128) {
        // dict insertion order (interleaved per layer)
        e1_0 = (const float*)d_in[0];   e2_0 = (const float*)d_in[1];
        e1_1 = (const float*)d_in[6];   e2_1 = (const float*)d_in[7];
        e1_2 = (const float*)d_in[12];  e2_2 = (const float*)d_in[13];
        c1_1 = (const float*)d_in[8];   c2_1 = (const float*)d_in[9];
        c1_2 = (const float*)d_in[14];  c2_2 = (const float*)d_in[15];
        a_1  = (const float*)d_in[10];  b_1  = (const float*)d_in[11];
        a_2  = (const float*)d_in[16];  b_2  = (const float*)d_in[17];
        link0 = (const float*)d_in[18]; link1 = (const float*)d_in[19];
    } else {
        // function-signature order (grouped)
        e1_0 = (const float*)d_in[0];   e1_1 = (const float*)d_in[1];
        e1_2 = (const float*)d_in[2];
        e2_0 = (const float*)d_in[3];   e2_1 = (const float*)d_in[4];
        e2_2 = (const float*)d_in[5];
        c1_1 = (const float*)d_in[7];   c1_2 = (const float*)d_in[8];
        c2_1 = (const float*)d_in[10];  c2_2 = (const float*)d_in[11];
        a_1  = (const float*)d_in[13];  a_2  = (const float*)d_in[14];
        b_1  = (const float*)d_in[16];  b_2  = (const float*)d_in[17];
        link0 = (const float*)d_in[18]; link1 = (const float*)d_in[19];
    }

    prep_kernel<<<299, 256>>>(e1_0, e1_1, e1_2, e2_0, e2_1, e2_2,
                              c1_1, c1_2, c2_1, c2_2, a_1, a_2, b_1, b_2,
                              link0, link1);

    dim3 grid(B / JT, B);   // (8, 512)
    dim3 blk(8, 64);
    avsl_main_kernel<<<grid, blk>>>((float*)d_out);
}